// round 3
// baseline (speedup 1.0000x reference)
#include <cuda_runtime.h>
#include <cuda_bf16.h>
#include <cstdint>

// Problem constants (fixed by the dataset)
#define MAX_NODES 100000
#define DIM 128
#define BM 128
#define BK 32

// Scratch: scatter-sum destination buffer (51.2 MB), static device global
// (no allocation allowed in kernel_launch). 16B-aligned for float4 atomics.
__device__ __align__(16) float g_msg[(size_t)MAX_NODES * DIM];

// Runtime-detected: is edge_index stored as int64 (1) or int32 (0)?
__device__ int g_idx64;

// ---------------------------------------------------------------------------
// Kernel 0: detect edge_index dtype. For int64 values < 2^31, every odd
// 32-bit word (the high half, little-endian) is zero. For int32 random node
// ids, the chance that 8 consecutive odd words are all zero is negligible.
// ---------------------------------------------------------------------------
__global__ void detect_kernel(const unsigned int* __restrict__ ei32) {
    unsigned int acc = 0;
#pragma unroll
    for (int k = 0; k < 8; ++k) acc |= ei32[2 * k + 1];
    g_idx64 = (acc == 0u) ? 1 : 0;
}

// ---------------------------------------------------------------------------
// Kernel 1: zero the message buffer
// ---------------------------------------------------------------------------
__global__ void zero_kernel(int n4) {
    int i = blockIdx.x * blockDim.x + threadIdx.x;
    if (i < n4) {
        ((float4*)g_msg)[i] = make_float4(0.f, 0.f, 0.f, 0.f);
    }
}

// ---------------------------------------------------------------------------
// Kernel 2: scatter-sum edges onto destination nodes.
// One warp per edge; each lane handles one float4 chunk (32 lanes * 4 = 128).
// Uses float4 vector atomicAdd (sm_90+) -> RED.128 to L2.
// ---------------------------------------------------------------------------
__global__ void scatter_kernel(const float* __restrict__ e,
                               const void* __restrict__ ei,
                               int nEdges, int nNodes) {
    int idx = blockIdx.x * blockDim.x + threadIdx.x;
    int edge = idx >> 5;
    if (edge >= nEdges) return;
    int c = (idx & 31) << 2;  // float offset 0..124

    int dst;
    if (g_idx64) {
        dst = (int)((const long long*)ei)[(size_t)nEdges + edge];  // row 1
    } else {
        dst = ((const int*)ei)[(size_t)nEdges + edge];
    }
    if ((unsigned)dst >= (unsigned)nNodes) return;  // never fault

    float4 v = *(const float4*)&e[(size_t)edge * DIM + c];
#if __CUDA_ARCH__ >= 900
    atomicAdd((float4*)&g_msg[(size_t)dst * DIM + c], v);
#else
    float* p = &g_msg[(size_t)dst * DIM + c];
    atomicAdd(p + 0, v.x);
    atomicAdd(p + 1, v.y);
    atomicAdd(p + 2, v.z);
    atomicAdd(p + 3, v.w);
#endif
}

// ---------------------------------------------------------------------------
// Kernel 3: fused MLP (4 GEMMs) + GroupNorm + residual.
// One block = 128 nodes. 256 threads as 16x16, each owning an 8x8 micro-tile
// (rows {ty*4..+3, 64+ty*4..+3}, cols {tx*4..+3, 64+tx*4..+3}).
// h tile lives in smem between layers; final layer normalized via shfl.
// ---------------------------------------------------------------------------

__device__ __forceinline__ void gemm_tile(const float* __restrict__ A, int lda,
                                          const float* __restrict__ Bs,
                                          int tx, int ty, float acc[8][8]) {
#pragma unroll 4
    for (int k = 0; k < BK; ++k) {
        float a[8];
#pragma unroll
        for (int i = 0; i < 4; ++i) {
            a[i]     = A[(ty * 4 + i) * lda + k];
            a[4 + i] = A[(64 + ty * 4 + i) * lda + k];
        }
        float4 q0 = *(const float4*)&Bs[k * DIM + tx * 4];
        float4 q1 = *(const float4*)&Bs[k * DIM + 64 + tx * 4];
        float b[8] = {q0.x, q0.y, q0.z, q0.w, q1.x, q1.y, q1.z, q1.w};
#pragma unroll
        for (int i = 0; i < 8; ++i)
#pragma unroll
            for (int j = 0; j < 8; ++j)
                acc[i][j] += a[i] * b[j];
    }
}

__device__ __forceinline__ void store_relu(float* __restrict__ Hs,
                                           float acc[8][8],
                                           const float* __restrict__ bias,
                                           int tx, int ty) {
    float4 bA = *(const float4*)&bias[tx * 4];
    float4 bB = *(const float4*)&bias[64 + tx * 4];
    float bb[8] = {bA.x, bA.y, bA.z, bA.w, bB.x, bB.y, bB.z, bB.w};
#pragma unroll
    for (int ri = 0; ri < 8; ++ri) {
        int r = (ri < 4) ? (ty * 4 + ri) : (64 + ty * 4 + ri - 4);
        float4 v0, v1;
        v0.x = fmaxf(acc[ri][0] + bb[0], 0.f);
        v0.y = fmaxf(acc[ri][1] + bb[1], 0.f);
        v0.z = fmaxf(acc[ri][2] + bb[2], 0.f);
        v0.w = fmaxf(acc[ri][3] + bb[3], 0.f);
        v1.x = fmaxf(acc[ri][4] + bb[4], 0.f);
        v1.y = fmaxf(acc[ri][5] + bb[5], 0.f);
        v1.z = fmaxf(acc[ri][6] + bb[6], 0.f);
        v1.w = fmaxf(acc[ri][7] + bb[7], 0.f);
        *(float4*)&Hs[r * DIM + tx * 4]      = v0;
        *(float4*)&Hs[r * DIM + 64 + tx * 4] = v1;
    }
}

__global__ __launch_bounds__(256, 2)
void mlp_kernel(const float* __restrict__ x,
                const float* __restrict__ W0, const float* __restrict__ b0,
                const float* __restrict__ Wh, const float* __restrict__ bh,
                const float* __restrict__ Wo, const float* __restrict__ bo,
                const float* __restrict__ gnw, const float* __restrict__ gnb,
                float* __restrict__ out, int nNodes) {
    extern __shared__ float sm[];
    float* Hs = sm;                 // 128*128
    float* As = sm + DIM * DIM;     // 128*32
    float* Bs = As + BM * BK;       // 32*128

    const int tid = threadIdx.x;
    const int tx = tid & 15, ty = tid >> 4;
    const int m0 = blockIdx.x * BM;

    float acc[8][8];
#pragma unroll
    for (int i = 0; i < 8; ++i)
#pragma unroll
        for (int j = 0; j < 8; ++j) acc[i][j] = 0.f;

    // ---- Layer 0: A = [x | msg], K = 256 ----
    for (int k0 = 0; k0 < 2 * DIM; k0 += BK) {
        const float* src = (k0 < DIM) ? x : (const float*)g_msg;
        int kc = (k0 < DIM) ? k0 : (k0 - DIM);
        // stage A chunk [128 x 32]
#pragma unroll
        for (int i = 0; i < 4; ++i) {
            int fid = i * 256 + tid;      // 0..1023 float4s
            int r = fid >> 3;
            int c = (fid & 7) << 2;
            float4 v = make_float4(0.f, 0.f, 0.f, 0.f);
            if (m0 + r < nNodes)
                v = *(const float4*)&src[(size_t)(m0 + r) * DIM + kc + c];
            *(float4*)&As[r * BK + c] = v;
        }
        // stage B chunk [32 x 128]
#pragma unroll
        for (int i = 0; i < 4; ++i) {
            int fid = i * 256 + tid;
            int kr = fid >> 5;
            int c = (fid & 31) << 2;
            *(float4*)&Bs[kr * DIM + c] = *(const float4*)&W0[(size_t)(k0 + kr) * DIM + c];
        }
        __syncthreads();
        gemm_tile(As, BK, Bs, tx, ty, acc);
        __syncthreads();
    }
    store_relu(Hs, acc, b0, tx, ty);
    __syncthreads();

    // ---- Hidden layers: A = Hs (in smem), K = 128 ----
    for (int l = 0; l < 2; ++l) {
#pragma unroll
        for (int i = 0; i < 8; ++i)
#pragma unroll
            for (int j = 0; j < 8; ++j) acc[i][j] = 0.f;
        const float* W = Wh + (size_t)l * DIM * DIM;
        for (int k0 = 0; k0 < DIM; k0 += BK) {
#pragma unroll
            for (int i = 0; i < 4; ++i) {
                int fid = i * 256 + tid;
                int kr = fid >> 5;
                int c = (fid & 31) << 2;
                *(float4*)&Bs[kr * DIM + c] = *(const float4*)&W[(size_t)(k0 + kr) * DIM + c];
            }
            __syncthreads();
            gemm_tile(Hs + k0, DIM, Bs, tx, ty, acc);
            __syncthreads();
        }
        store_relu(Hs, acc, bh + l * DIM, tx, ty);
        __syncthreads();
    }

    // ---- Output layer: no relu ----
#pragma unroll
    for (int i = 0; i < 8; ++i)
#pragma unroll
        for (int j = 0; j < 8; ++j) acc[i][j] = 0.f;
    for (int k0 = 0; k0 < DIM; k0 += BK) {
#pragma unroll
        for (int i = 0; i < 4; ++i) {
            int fid = i * 256 + tid;
            int kr = fid >> 5;
            int c = (fid & 31) << 2;
            *(float4*)&Bs[kr * DIM + c] = *(const float4*)&Wo[(size_t)(k0 + kr) * DIM + c];
        }
        __syncthreads();
        gemm_tile(Hs + k0, DIM, Bs, tx, ty, acc);
        __syncthreads();
    }

    // bias
    {
        float4 bA = *(const float4*)&bo[tx * 4];
        float4 bB = *(const float4*)&bo[64 + tx * 4];
        float bb[8] = {bA.x, bA.y, bA.z, bA.w, bB.x, bB.y, bB.z, bB.w};
#pragma unroll
        for (int i = 0; i < 8; ++i)
#pragma unroll
            for (int j = 0; j < 8; ++j) acc[i][j] += bb[j];
    }

    // GroupNorm(1 group) + affine + residual
    float4 gwA = *(const float4*)&gnw[tx * 4];
    float4 gwB = *(const float4*)&gnw[64 + tx * 4];
    float4 gbA = *(const float4*)&gnb[tx * 4];
    float4 gbB = *(const float4*)&gnb[64 + tx * 4];
    float gw[8] = {gwA.x, gwA.y, gwA.z, gwA.w, gwB.x, gwB.y, gwB.z, gwB.w};
    float gb[8] = {gbA.x, gbA.y, gbA.z, gbA.w, gbB.x, gbB.y, gbB.z, gbB.w};

#pragma unroll
    for (int ri = 0; ri < 8; ++ri) {
        int r = (ri < 4) ? (ty * 4 + ri) : (64 + ty * 4 + ri - 4);
        float s = 0.f, sq = 0.f;
#pragma unroll
        for (int j = 0; j < 8; ++j) {
            s += acc[ri][j];
            sq += acc[ri][j] * acc[ri][j];
        }
        // reduce across the 16 tx lanes (lane = (ty&1)*16 + tx; offsets < 16
        // permute only the tx bits, so the reduction stays within the row group)
#pragma unroll
        for (int off = 8; off >= 1; off >>= 1) {
            s  += __shfl_xor_sync(0xffffffffu, s, off);
            sq += __shfl_xor_sync(0xffffffffu, sq, off);
        }
        float mean = s * (1.f / 128.f);
        float var = sq * (1.f / 128.f) - mean * mean;
        float rstd = rsqrtf(var + 1e-5f);
        if (m0 + r < nNodes) {
            const float* xr = &x[(size_t)(m0 + r) * DIM];
            float4 x0 = *(const float4*)&xr[tx * 4];
            float4 x1 = *(const float4*)&xr[64 + tx * 4];
            float4 o0, o1;
            o0.x = (acc[ri][0] - mean) * rstd * gw[0] + gb[0] + x0.x;
            o0.y = (acc[ri][1] - mean) * rstd * gw[1] + gb[1] + x0.y;
            o0.z = (acc[ri][2] - mean) * rstd * gw[2] + gb[2] + x0.z;
            o0.w = (acc[ri][3] - mean) * rstd * gw[3] + gb[3] + x0.w;
            o1.x = (acc[ri][4] - mean) * rstd * gw[4] + gb[4] + x1.x;
            o1.y = (acc[ri][5] - mean) * rstd * gw[5] + gb[5] + x1.y;
            o1.z = (acc[ri][6] - mean) * rstd * gw[6] + gb[6] + x1.z;
            o1.w = (acc[ri][7] - mean) * rstd * gw[7] + gb[7] + x1.w;
            float* orow = &out[(size_t)(m0 + r) * DIM];
            *(float4*)&orow[tx * 4]      = o0;
            *(float4*)&orow[64 + tx * 4] = o1;
        }
    }
}

// ---------------------------------------------------------------------------
extern "C" void kernel_launch(void* const* d_in, const int* in_sizes, int n_in,
                              void* d_out, int out_size) {
    const float* x  = (const float*)d_in[0];
    const float* e  = (const float*)d_in[1];
    const void*  ei = d_in[2];
    const float* W0 = (const float*)d_in[3];
    const float* b0 = (const float*)d_in[4];
    const float* Wh = (const float*)d_in[5];
    const float* bh = (const float*)d_in[6];
    const float* Wo = (const float*)d_in[7];
    const float* bo = (const float*)d_in[8];
    const float* gnw = (const float*)d_in[9];
    const float* gnb = (const float*)d_in[10];
    float* out = (float*)d_out;

    int nNodes = in_sizes[0] / DIM;
    int nEdges = in_sizes[1] / DIM;
    if (nNodes > MAX_NODES) nNodes = MAX_NODES;

    const int smem_bytes = (DIM * DIM + BM * BK + BK * DIM) * sizeof(float);  // 96 KB
    cudaFuncSetAttribute(mlp_kernel, cudaFuncAttributeMaxDynamicSharedMemorySize,
                         smem_bytes);

    // 0) detect edge_index dtype (int64 vs int32)
    detect_kernel<<<1, 1>>>((const unsigned int*)ei);

    // 1) zero msg buffer
    int n4 = nNodes * DIM / 4;
    zero_kernel<<<(n4 + 255) / 256, 256>>>(n4);

    // 2) scatter-sum
    long long total = (long long)nEdges * 32;
    int sblocks = (int)((total + 255) / 256);
    scatter_kernel<<<sblocks, 256>>>(e, ei, nEdges, nNodes);

    // 3) fused MLP + GroupNorm + residual
    int mblocks = (nNodes + BM - 1) / BM;
    mlp_kernel<<<mblocks, 256, smem_bytes>>>(x, W0, b0, Wh, bh, Wo, bo,
                                             gnw, gnb, out, nNodes);
}

// round 5
// speedup vs baseline: 1.1071x; 1.1071x over previous
#include <cuda_runtime.h>
#include <cuda_bf16.h>
#include <cstdint>

// ---------------------------------------------------------------------------
// Problem constants
// ---------------------------------------------------------------------------
#define MAX_NODES 100000
#define DIM 128

// Scratch (no allocation allowed in kernel_launch)
__device__ __align__(16) float g_msg[(size_t)MAX_NODES * DIM];
__device__ int g_idx64;
// Pre-transposed bf16 hi/lo weights, [n][k] layout (k contiguous), plain rows.
// 5 chunks: W0[k<128], W0[k>=128], Wh[0], Wh[1], Wo. Each 128x128 bf16.
__device__ __align__(16) __nv_bfloat16 g_whi[5][128 * 128];
__device__ __align__(16) __nv_bfloat16 g_wlo[5][128 * 128];

// ---------------------------------------------------------------------------
// Helpers
// ---------------------------------------------------------------------------
__device__ __forceinline__ uint32_t smem_to_u32(const void* p) {
    uint32_t a;
    asm("{ .reg .u64 t; cvta.to.shared.u64 t, %1; cvt.u32.u64 %0, t; }"
        : "=r"(a) : "l"(p));
    return a;
}

__device__ __forceinline__ void ldsm4(uint32_t* r, uint32_t addr) {
    asm volatile("ldmatrix.sync.aligned.m8n8.x4.shared.b16 {%0,%1,%2,%3}, [%4];\n"
                 : "=r"(r[0]), "=r"(r[1]), "=r"(r[2]), "=r"(r[3]) : "r"(addr));
}

__device__ __forceinline__ void mma16816(float* c, const uint32_t* a,
                                         const uint32_t* b) {
    asm volatile(
        "mma.sync.aligned.m16n8k16.row.col.f32.bf16.bf16.f32 "
        "{%0,%1,%2,%3}, {%4,%5,%6,%7}, {%8,%9}, {%0,%1,%2,%3};\n"
        : "+f"(c[0]), "+f"(c[1]), "+f"(c[2]), "+f"(c[3])
        : "r"(a[0]), "r"(a[1]), "r"(a[2]), "r"(a[3]), "r"(b[0]), "r"(b[1]));
}

// pack two floats into bf16 hi pair + lo pair
__device__ __forceinline__ uint32_t pack_hilo(float v0, float v1, uint32_t& lo) {
    __nv_bfloat16 h0 = __float2bfloat16(v0);
    __nv_bfloat16 h1 = __float2bfloat16(v1);
    __nv_bfloat16 l0 = __float2bfloat16(v0 - __bfloat162float(h0));
    __nv_bfloat16 l1 = __float2bfloat16(v1 - __bfloat162float(h1));
    __nv_bfloat162 hp; hp.x = h0; hp.y = h1;
    __nv_bfloat162 lp; lp.x = l0; lp.y = l1;
    lo = *(uint32_t*)&lp;
    return *(uint32_t*)&hp;
}

// Padded smem tile geometry: 128 rows x 128 bf16, row stride 272 B (17 x 16B
// -> ldmatrix row addresses with stride 272 walk all 8 bank-groups).
#define ROWB 272
#define TILE_BYTES_PAD (128 * ROWB)   // 34816

// ---------------------------------------------------------------------------
// Kernel 0: detect edge_index dtype (int64 high words all zero)
// ---------------------------------------------------------------------------
__global__ void detect_kernel(const unsigned int* __restrict__ ei32) {
    unsigned int acc = 0;
#pragma unroll
    for (int k = 0; k < 8; ++k) acc |= ei32[2 * k + 1];
    g_idx64 = (acc == 0u) ? 1 : 0;
}

// ---------------------------------------------------------------------------
// Kernel 1: zero the message buffer
// ---------------------------------------------------------------------------
__global__ void zero_kernel(int n4) {
    int i = blockIdx.x * blockDim.x + threadIdx.x;
    if (i < n4) ((float4*)g_msg)[i] = make_float4(0.f, 0.f, 0.f, 0.f);
}

// ---------------------------------------------------------------------------
// Kernel 2: scatter-sum (one warp per edge, float4 RED.128)
// ---------------------------------------------------------------------------
__global__ void scatter_kernel(const float* __restrict__ e,
                               const void* __restrict__ ei,
                               int nEdges, int nNodes) {
    int idx = blockIdx.x * blockDim.x + threadIdx.x;
    int edge = idx >> 5;
    if (edge >= nEdges) return;
    int c = (idx & 31) << 2;
    int dst;
    if (g_idx64) dst = (int)((const long long*)ei)[(size_t)nEdges + edge];
    else         dst = ((const int*)ei)[(size_t)nEdges + edge];
    if ((unsigned)dst >= (unsigned)nNodes) return;
    float4 v = *(const float4*)&e[(size_t)edge * DIM + c];
    atomicAdd((float4*)&g_msg[(size_t)dst * DIM + c], v);
}

// ---------------------------------------------------------------------------
// Kernel 3: weight prep. B[n][k] = W[k][n], bf16 hi/lo.
// ---------------------------------------------------------------------------
__global__ void prep_weights(const float* __restrict__ W0,
                             const float* __restrict__ Wh,
                             const float* __restrict__ Wo) {
    int l = blockIdx.x;  // 0..4
    const float* src;
    if (l == 0)      src = W0;
    else if (l == 1) src = W0 + 128 * 128;
    else if (l == 2) src = Wh;
    else if (l == 3) src = Wh + 128 * 128;
    else             src = Wo;
    __nv_bfloat16* dh = g_whi[l];
    __nv_bfloat16* dl = g_wlo[l];
    for (int i = threadIdx.x; i < 128 * 128; i += blockDim.x) {
        int n = i >> 7, k = i & 127;
        float w = src[k * 128 + n];
        __nv_bfloat16 hi = __float2bfloat16(w);
        dh[i] = hi;
        dl[i] = __float2bfloat16(w - __bfloat162float(hi));
    }
}

// ---------------------------------------------------------------------------
// MLP kernel (mma.sync bf16 hi/lo). 128 nodes per block, 256 threads.
// Warp (wid&3) -> 32-row slice; (wid>>2) -> 64-col half. Per warp: 2 m-tiles
// (m16) x 8 n-tiles (n8), acc[2][8][4].
// ---------------------------------------------------------------------------
__device__ __forceinline__ void stage_A(const float* __restrict__ src, int m0,
                                        int nNodes, unsigned char* Ahi,
                                        unsigned char* Alo, int tid) {
#pragma unroll
    for (int i = 0; i < 16; ++i) {
        int id = i * 256 + tid;        // 0..4095 float4s
        int row = id >> 5;
        int k0 = (id & 31) << 2;
        float4 v = make_float4(0.f, 0.f, 0.f, 0.f);
        int node = m0 + row;
        if (node < nNodes) v = *(const float4*)&src[(size_t)node * DIM + k0];
        uint32_t l01, l23;
        uint32_t h01 = pack_hilo(v.x, v.y, l01);
        uint32_t h23 = pack_hilo(v.z, v.w, l23);
        uint2 uh; uh.x = h01; uh.y = h23;
        uint2 ul; ul.x = l01; ul.y = l23;
        *(uint2*)(Ahi + row * ROWB + k0 * 2) = uh;
        *(uint2*)(Alo + row * ROWB + k0 * 2) = ul;
    }
}

__device__ __forceinline__ void stage_B(int l, unsigned char* Bhi,
                                        unsigned char* Blo, int tid) {
    const float4* sh = (const float4*)g_whi[l];
    const float4* sl = (const float4*)g_wlo[l];
#pragma unroll
    for (int i = 0; i < 8; ++i) {
        int id = i * 256 + tid;        // 0..2047 float4s (16 per row)
        int row = id >> 4;
        int c16 = id & 15;
        *(float4*)(Bhi + row * ROWB + c16 * 16) = sh[id];
        *(float4*)(Blo + row * ROWB + c16 * 16) = sl[id];
    }
}

__device__ __forceinline__ void clear_acc(float acc[2][8][4]) {
#pragma unroll
    for (int m = 0; m < 2; ++m)
#pragma unroll
        for (int n = 0; n < 8; ++n)
#pragma unroll
            for (int c = 0; c < 4; ++c) acc[m][n][c] = 0.f;
}

// One 128x128x128 GEMM unit accumulating into acc.
// aoff/boff: per-lane ldmatrix byte offsets within a tile.
__device__ __forceinline__ void gemm_unit(float acc[2][8][4],
                                          uint32_t AHI, uint32_t ALO,
                                          uint32_t BHI, uint32_t BLO,
                                          uint32_t aoff, uint32_t boff) {
#pragma unroll
    for (int k0 = 0; k0 < 128; k0 += 16) {
        uint32_t ah[2][4], al[2][4];
        ldsm4(ah[0], AHI + aoff + k0 * 2);
        ldsm4(ah[1], AHI + aoff + 16 * ROWB + k0 * 2);
        ldsm4(al[0], ALO + aoff + k0 * 2);
        ldsm4(al[1], ALO + aoff + 16 * ROWB + k0 * 2);
#pragma unroll
        for (int g = 0; g < 4; ++g) {
            uint32_t bh[4], bl[4];
            ldsm4(bh, BHI + boff + g * 16 * ROWB + k0 * 2);
            ldsm4(bl, BLO + boff + g * 16 * ROWB + k0 * 2);
#pragma unroll
            for (int t = 0; t < 2; ++t) {
                int nt = g * 2 + t;
#pragma unroll
                for (int mt = 0; mt < 2; ++mt) {
                    mma16816(acc[mt][nt], ah[mt], bh + t * 2);
                    mma16816(acc[mt][nt], ah[mt], bl + t * 2);
                    mma16816(acc[mt][nt], al[mt], bh + t * 2);
                }
            }
        }
    }
}

// ReLU epilogue: acc + bias -> relu -> bf16 hi/lo into A smem for next layer.
__device__ __forceinline__ void epi_relu(float acc[2][8][4],
                                         const float* __restrict__ sbias,
                                         unsigned char* Ahi, unsigned char* Alo,
                                         int warp_m, int warp_n, int lane) {
    int rbase = warp_m * 32 + (lane >> 2);
    int cbase = warp_n * 64 + 2 * (lane & 3);
#pragma unroll
    for (int mt = 0; mt < 2; ++mt) {
#pragma unroll
        for (int nt = 0; nt < 8; ++nt) {
            int c = cbase + nt * 8;
            float bb0 = sbias[c], bb1 = sbias[c + 1];
            int r0 = rbase + mt * 16;
            float v0 = fmaxf(acc[mt][nt][0] + bb0, 0.f);
            float v1 = fmaxf(acc[mt][nt][1] + bb1, 0.f);
            float v2 = fmaxf(acc[mt][nt][2] + bb0, 0.f);
            float v3 = fmaxf(acc[mt][nt][3] + bb1, 0.f);
            uint32_t lo;
            uint32_t hi = pack_hilo(v0, v1, lo);
            *(uint32_t*)(Ahi + r0 * ROWB + c * 2) = hi;
            *(uint32_t*)(Alo + r0 * ROWB + c * 2) = lo;
            hi = pack_hilo(v2, v3, lo);
            *(uint32_t*)(Ahi + (r0 + 8) * ROWB + c * 2) = hi;
            *(uint32_t*)(Alo + (r0 + 8) * ROWB + c * 2) = lo;
        }
    }
}

#define SMEM_AOFF 5120
#define SMEM_TOTAL_MLP (SMEM_AOFF + 4 * TILE_BYTES_PAD)   // 144384

__global__ __launch_bounds__(256, 1)
void mlp_mma_kernel(const float* __restrict__ x,
                    const float* __restrict__ b0v,
                    const float* __restrict__ bhv,
                    const float* __restrict__ bov,
                    const float* __restrict__ gnw, const float* __restrict__ gnb,
                    float* __restrict__ out, int nNodes) {
    extern __shared__ unsigned char smem[];
    float* sb   = (float*)smem;            // [4][128] biases: b0, bh0, bh1, bo
    float* sgw  = (float*)(smem + 2048);
    float* sgb  = (float*)(smem + 2560);
    float* ps   = (float*)(smem + 3072);   // [2][128]
    float* pq   = (float*)(smem + 4096);   // [2][128]
    unsigned char* Ahi = smem + SMEM_AOFF;
    unsigned char* Alo = Ahi + TILE_BYTES_PAD;
    unsigned char* Bhi = Alo + TILE_BYTES_PAD;
    unsigned char* Blo = Bhi + TILE_BYTES_PAD;

    const uint32_t sb32 = smem_to_u32(smem);
    const uint32_t AHI = sb32 + SMEM_AOFF;
    const uint32_t ALO = AHI + TILE_BYTES_PAD;
    const uint32_t BHI = ALO + TILE_BYTES_PAD;
    const uint32_t BLO = BHI + TILE_BYTES_PAD;

    const int tid = threadIdx.x;
    const int wid = tid >> 5, lane = tid & 31;
    const int warp_m = wid & 3, warp_n = wid >> 2;
    const int m0 = blockIdx.x * 128;

    // per-lane ldmatrix offsets
    const uint32_t aoff =
        (uint32_t)(warp_m * 32 + (lane & 15)) * ROWB + (((lane >> 4) & 1) * 8) * 2;
    const uint32_t boff =
        (uint32_t)(warp_n * 64 + ((lane >> 4) & 1) * 8 + (lane & 7)) * ROWB +
        (((lane >> 3) & 1) * 8) * 2;

    // load constants
    if (tid < 128) {
        sb[tid]       = b0v[tid];
        sb[128 + tid] = bhv[tid];
        sb[256 + tid] = bhv[128 + tid];
        sb[384 + tid] = bov[tid];
        sgw[tid] = gnw[tid];
        sgb[tid] = gnb[tid];
    }

    float acc[2][8][4];
    clear_acc(acc);

    // ---- layer 0, part 1: A = x, B = W0[k<128] ----
    stage_A(x, m0, nNodes, Ahi, Alo, tid);
    stage_B(0, Bhi, Blo, tid);
    __syncthreads();
    gemm_unit(acc, AHI, ALO, BHI, BLO, aoff, boff);
    __syncthreads();

    // ---- layer 0, part 2: A = msg, B = W0[k>=128] (accumulate) ----
    stage_A((const float*)g_msg, m0, nNodes, Ahi, Alo, tid);
    stage_B(1, Bhi, Blo, tid);
    __syncthreads();
    gemm_unit(acc, AHI, ALO, BHI, BLO, aoff, boff);
    __syncthreads();

    // ---- hidden layers ----
#pragma unroll
    for (int l = 0; l < 2; ++l) {
        epi_relu(acc, sb + l * 128, Ahi, Alo, warp_m, warp_n, lane);
        stage_B(2 + l, Bhi, Blo, tid);
        __syncthreads();
        clear_acc(acc);
        gemm_unit(acc, AHI, ALO, BHI, BLO, aoff, boff);
        __syncthreads();
    }

    // ---- output layer ----
    epi_relu(acc, sb + 256, Ahi, Alo, warp_m, warp_n, lane);
    stage_B(4, Bhi, Blo, tid);
    __syncthreads();
    clear_acc(acc);
    gemm_unit(acc, AHI, ALO, BHI, BLO, aoff, boff);

    // ---- GroupNorm + affine + residual ----
    const int rq = lane >> 2;
    const int cbase = warp_n * 64 + 2 * (lane & 3);
    // bias add
#pragma unroll
    for (int mt = 0; mt < 2; ++mt)
#pragma unroll
        for (int nt = 0; nt < 8; ++nt) {
            int c = cbase + nt * 8;
            acc[mt][nt][0] += sb[384 + c];
            acc[mt][nt][1] += sb[384 + c + 1];
            acc[mt][nt][2] += sb[384 + c];
            acc[mt][nt][3] += sb[384 + c + 1];
        }
    // row partial sums over this warp's 64 cols
    float s[4] = {0.f, 0.f, 0.f, 0.f}, q[4] = {0.f, 0.f, 0.f, 0.f};
#pragma unroll
    for (int mt = 0; mt < 2; ++mt)
#pragma unroll
        for (int nt = 0; nt < 8; ++nt) {
            float a0 = acc[mt][nt][0], a1 = acc[mt][nt][1];
            float a2 = acc[mt][nt][2], a3 = acc[mt][nt][3];
            s[mt * 2]     += a0 + a1;
            q[mt * 2]     += a0 * a0 + a1 * a1;
            s[mt * 2 + 1] += a2 + a3;
            q[mt * 2 + 1] += a2 * a2 + a3 * a3;
        }
#pragma unroll
    for (int off = 1; off <= 2; off <<= 1) {
#pragma unroll
        for (int i = 0; i < 4; ++i) {
            s[i] += __shfl_xor_sync(0xffffffffu, s[i], off);
            q[i] += __shfl_xor_sync(0xffffffffu, q[i], off);
        }
    }
    if ((lane & 3) == 0) {
        int r0 = warp_m * 32 + rq;
        ps[warp_n * 128 + r0]      = s[0];
        ps[warp_n * 128 + r0 + 8]  = s[1];
        ps[warp_n * 128 + r0 + 16] = s[2];
        ps[warp_n * 128 + r0 + 24] = s[3];
        pq[warp_n * 128 + r0]      = q[0];
        pq[warp_n * 128 + r0 + 8]  = q[1];
        pq[warp_n * 128 + r0 + 16] = q[2];
        pq[warp_n * 128 + r0 + 24] = q[3];
    }
    __syncthreads();
#pragma unroll
    for (int mt = 0; mt < 2; ++mt) {
#pragma unroll
        for (int h = 0; h < 2; ++h) {
            int r = warp_m * 32 + mt * 16 + h * 8 + rq;
            float ts = ps[r] + ps[128 + r];
            float tq = pq[r] + pq[128 + r];
            float mean = ts * (1.f / 128.f);
            float var = tq * (1.f / 128.f) - mean * mean;
            float rstd = rsqrtf(var + 1e-5f);
            int node = m0 + r;
            if (node < nNodes) {
#pragma unroll
                for (int nt = 0; nt < 8; ++nt) {
                    int c = cbase + nt * 8;
                    float v0 = acc[mt][nt][h * 2 + 0];
                    float v1 = acc[mt][nt][h * 2 + 1];
                    float2 xv = *(const float2*)&x[(size_t)node * DIM + c];
                    float2 o;
                    o.x = (v0 - mean) * rstd * sgw[c]     + sgb[c]     + xv.x;
                    o.y = (v1 - mean) * rstd * sgw[c + 1] + sgb[c + 1] + xv.y;
                    *(float2*)&out[(size_t)node * DIM + c] = o;
                }
            }
        }
    }
}

// ---------------------------------------------------------------------------
extern "C" void kernel_launch(void* const* d_in, const int* in_sizes, int n_in,
                              void* d_out, int out_size) {
    const float* x  = (const float*)d_in[0];
    const float* e  = (const float*)d_in[1];
    const void*  ei = d_in[2];
    const float* W0 = (const float*)d_in[3];
    const float* b0 = (const float*)d_in[4];
    const float* Wh = (const float*)d_in[5];
    const float* bh = (const float*)d_in[6];
    const float* Wo = (const float*)d_in[7];
    const float* bo = (const float*)d_in[8];
    const float* gnw = (const float*)d_in[9];
    const float* gnb = (const float*)d_in[10];
    float* out = (float*)d_out;

    int nNodes = in_sizes[0] / DIM;
    int nEdges = in_sizes[1] / DIM;
    if (nNodes > MAX_NODES) nNodes = MAX_NODES;

    cudaFuncSetAttribute(mlp_mma_kernel, cudaFuncAttributeMaxDynamicSharedMemorySize,
                         SMEM_TOTAL_MLP);

    // 0) detect edge_index dtype
    detect_kernel<<<1, 1>>>((const unsigned int*)ei);

    // 1) zero msg buffer
    int n4 = nNodes * DIM / 4;
    zero_kernel<<<(n4 + 255) / 256, 256>>>(n4);

    // 2) weight prep (independent of scatter)
    prep_weights<<<5, 256>>>(W0, Wh, Wo);

    // 3) scatter-sum
    long long total = (long long)nEdges * 32;
    int sblocks = (int)((total + 255) / 256);
    scatter_kernel<<<sblocks, 256>>>(e, ei, nEdges, nNodes);

    // 4) fused tensor-core MLP + GroupNorm + residual
    int mblocks = (nNodes + 127) / 128;
    mlp_mma_kernel<<<mblocks, 256, SMEM_TOTAL_MLP>>>(x, b0, bh, bo, gnw, gnb,
                                                     out, nNodes);
}

// round 6
// speedup vs baseline: 1.8242x; 1.6476x over previous
#include <cuda_runtime.h>
#include <cuda_bf16.h>
#include <cstdint>

// ---------------------------------------------------------------------------
// Problem constants
// ---------------------------------------------------------------------------
#define MAX_NODES 100000
#define MAX_EDGES 1700000
#define DIM 128

// Scratch (no allocation allowed in kernel_launch)
__device__ __align__(16) float g_msg[(size_t)MAX_NODES * DIM];
__device__ int g_idx64;
__device__ __align__(16) __nv_bfloat16 g_whi[5][128 * 128];
__device__ __align__(16) __nv_bfloat16 g_wlo[5][128 * 128];
// CSR scratch
__device__ int g_cnt[MAX_NODES];
__device__ int g_off[MAX_NODES];
__device__ int g_cursor[MAX_NODES];
__device__ int g_eid[MAX_EDGES];
__device__ int g_bsum[256];
__device__ int g_bsumx[256];

// ---------------------------------------------------------------------------
// Helpers
// ---------------------------------------------------------------------------
__device__ __forceinline__ uint32_t smem_to_u32(const void* p) {
    uint32_t a;
    asm("{ .reg .u64 t; cvta.to.shared.u64 t, %1; cvt.u32.u64 %0, t; }"
        : "=r"(a) : "l"(p));
    return a;
}

__device__ __forceinline__ void ldsm4(uint32_t* r, uint32_t addr) {
    asm volatile("ldmatrix.sync.aligned.m8n8.x4.shared.b16 {%0,%1,%2,%3}, [%4];\n"
                 : "=r"(r[0]), "=r"(r[1]), "=r"(r[2]), "=r"(r[3]) : "r"(addr));
}

__device__ __forceinline__ void mma16816(float* c, const uint32_t* a,
                                         const uint32_t* b) {
    asm volatile(
        "mma.sync.aligned.m16n8k16.row.col.f32.bf16.bf16.f32 "
        "{%0,%1,%2,%3}, {%4,%5,%6,%7}, {%8,%9}, {%0,%1,%2,%3};\n"
        : "+f"(c[0]), "+f"(c[1]), "+f"(c[2]), "+f"(c[3])
        : "r"(a[0]), "r"(a[1]), "r"(a[2]), "r"(a[3]), "r"(b[0]), "r"(b[1]));
}

__device__ __forceinline__ uint32_t pack_hilo(float v0, float v1, uint32_t& lo) {
    __nv_bfloat16 h0 = __float2bfloat16(v0);
    __nv_bfloat16 h1 = __float2bfloat16(v1);
    __nv_bfloat16 l0 = __float2bfloat16(v0 - __bfloat162float(h0));
    __nv_bfloat16 l1 = __float2bfloat16(v1 - __bfloat162float(h1));
    __nv_bfloat162 hp; hp.x = h0; hp.y = h1;
    __nv_bfloat162 lp; lp.x = l0; lp.y = l1;
    lo = *(uint32_t*)&lp;
    return *(uint32_t*)&hp;
}

// Read destination node id of an edge (dtype-agnostic)
__device__ __forceinline__ int edge_dst(const void* ei, int nEdges, int edge) {
    if (g_idx64) return (int)((const long long*)ei)[(size_t)nEdges + edge];
    return ((const int*)ei)[(size_t)nEdges + edge];
}

#define ROWB 272
#define TILE_BYTES_PAD (128 * ROWB)   // 34816

// ---------------------------------------------------------------------------
// Kernel 0: detect edge_index dtype (int64 high words all zero)
// ---------------------------------------------------------------------------
__global__ void detect_kernel(const unsigned int* __restrict__ ei32) {
    unsigned int acc = 0;
#pragma unroll
    for (int k = 0; k < 8; ++k) acc |= ei32[2 * k + 1];
    g_idx64 = (acc == 0u) ? 1 : 0;
}

// ---------------------------------------------------------------------------
// CSR build kernels
// ---------------------------------------------------------------------------
__global__ void zero_cnt_kernel(int nNodes) {
    int i = blockIdx.x * blockDim.x + threadIdx.x;
    if (i < nNodes) g_cnt[i] = 0;
}

__global__ void hist_kernel(const void* __restrict__ ei, int nEdges, int nNodes) {
    int i = blockIdx.x * blockDim.x + threadIdx.x;
    if (i >= nEdges) return;
    int dst = edge_dst(ei, nEdges, i);
    if ((unsigned)dst < (unsigned)nNodes) atomicAdd(&g_cnt[dst], 1);
}

// Block-level exclusive scan (1024 threads/block)
__global__ void scan1_kernel(int nNodes) {
    __shared__ int wsum[32];
    int i = blockIdx.x * 1024 + threadIdx.x;
    int lane = threadIdx.x & 31, w = threadIdx.x >> 5;
    int v = (i < nNodes) ? g_cnt[i] : 0;
    int inc = v;
#pragma unroll
    for (int off = 1; off < 32; off <<= 1) {
        int t = __shfl_up_sync(0xffffffffu, inc, off);
        if (lane >= off) inc += t;
    }
    if (lane == 31) wsum[w] = inc;
    __syncthreads();
    if (w == 0) {
        int s = (lane < 32) ? wsum[lane] : 0;
#pragma unroll
        for (int off = 1; off < 32; off <<= 1) {
            int t = __shfl_up_sync(0xffffffffu, s, off);
            if (lane >= off) s += t;
        }
        wsum[lane] = s;
    }
    __syncthreads();
    int base = (w > 0) ? wsum[w - 1] : 0;
    int excl = base + inc - v;
    if (i < nNodes) g_off[i] = excl;
    if (threadIdx.x == 1023) g_bsum[blockIdx.x] = base + inc;
}

__global__ void scan2_kernel(int nblocks) {
    if (threadIdx.x == 0) {
        int s = 0;
        for (int b = 0; b < nblocks; ++b) { g_bsumx[b] = s; s += g_bsum[b]; }
    }
}

__global__ void scan3_kernel(int nNodes) {
    int i = blockIdx.x * 1024 + threadIdx.x;
    if (i < nNodes) {
        int o = g_off[i] + g_bsumx[blockIdx.x];
        g_off[i] = o;
        g_cursor[i] = o;
    }
}

__global__ void fill_kernel(const void* __restrict__ ei, int nEdges, int nNodes) {
    int i = blockIdx.x * blockDim.x + threadIdx.x;
    if (i >= nEdges) return;
    int dst = edge_dst(ei, nEdges, i);
    if ((unsigned)dst >= (unsigned)nNodes) return;
    int pos = atomicAdd(&g_cursor[dst], 1);
    g_eid[pos] = i;
}

// ---------------------------------------------------------------------------
// Gather: one warp per node, lane c owns float4 chunk c. No atomics.
// ---------------------------------------------------------------------------
__global__ void gather_kernel(const float* __restrict__ e, int nNodes) {
    int gid = blockIdx.x * blockDim.x + threadIdx.x;
    int node = gid >> 5;
    if (node >= nNodes) return;
    int lane = gid & 31;
    int c = lane << 2;
    int start = g_off[node];
    int n = g_cnt[node];
    float4 acc = make_float4(0.f, 0.f, 0.f, 0.f);
    int i = 0;
    for (; i + 2 <= n; i += 2) {
        int e0 = g_eid[start + i];
        int e1 = g_eid[start + i + 1];
        float4 v0 = *(const float4*)&e[(size_t)e0 * DIM + c];
        float4 v1 = *(const float4*)&e[(size_t)e1 * DIM + c];
        acc.x += v0.x; acc.y += v0.y; acc.z += v0.z; acc.w += v0.w;
        acc.x += v1.x; acc.y += v1.y; acc.z += v1.z; acc.w += v1.w;
    }
    if (i < n) {
        int e0 = g_eid[start + i];
        float4 v0 = *(const float4*)&e[(size_t)e0 * DIM + c];
        acc.x += v0.x; acc.y += v0.y; acc.z += v0.z; acc.w += v0.w;
    }
    *(float4*)&g_msg[(size_t)node * DIM + c] = acc;
}

// ---------------------------------------------------------------------------
// Kernel: weight prep. B[n][k] = W[k][n], bf16 hi/lo.
// ---------------------------------------------------------------------------
__global__ void prep_weights(const float* __restrict__ W0,
                             const float* __restrict__ Wh,
                             const float* __restrict__ Wo) {
    int l = blockIdx.x;  // 0..4
    const float* src;
    if (l == 0)      src = W0;
    else if (l == 1) src = W0 + 128 * 128;
    else if (l == 2) src = Wh;
    else if (l == 3) src = Wh + 128 * 128;
    else             src = Wo;
    __nv_bfloat16* dh = g_whi[l];
    __nv_bfloat16* dl = g_wlo[l];
    for (int i = threadIdx.x; i < 128 * 128; i += blockDim.x) {
        int n = i >> 7, k = i & 127;
        float w = src[k * 128 + n];
        __nv_bfloat16 hi = __float2bfloat16(w);
        dh[i] = hi;
        dl[i] = __float2bfloat16(w - __bfloat162float(hi));
    }
}

// ---------------------------------------------------------------------------
// MLP kernel (mma.sync bf16 hi/lo). 128 nodes per block, 256 threads.
// ---------------------------------------------------------------------------
__device__ __forceinline__ void stage_A(const float* __restrict__ src, int m0,
                                        int nNodes, unsigned char* Ahi,
                                        unsigned char* Alo, int tid) {
#pragma unroll
    for (int i = 0; i < 16; ++i) {
        int id = i * 256 + tid;        // 0..4095 float4s
        int row = id >> 5;
        int k0 = (id & 31) << 2;
        float4 v = make_float4(0.f, 0.f, 0.f, 0.f);
        int node = m0 + row;
        if (node < nNodes) v = *(const float4*)&src[(size_t)node * DIM + k0];
        uint32_t l01, l23;
        uint32_t h01 = pack_hilo(v.x, v.y, l01);
        uint32_t h23 = pack_hilo(v.z, v.w, l23);
        uint2 uh; uh.x = h01; uh.y = h23;
        uint2 ul; ul.x = l01; ul.y = l23;
        *(uint2*)(Ahi + row * ROWB + k0 * 2) = uh;
        *(uint2*)(Alo + row * ROWB + k0 * 2) = ul;
    }
}

__device__ __forceinline__ void stage_B(int l, unsigned char* Bhi,
                                        unsigned char* Blo, int tid) {
    const float4* sh = (const float4*)g_whi[l];
    const float4* sl = (const float4*)g_wlo[l];
#pragma unroll
    for (int i = 0; i < 8; ++i) {
        int id = i * 256 + tid;        // 0..2047 float4s (16 per row)
        int row = id >> 4;
        int c16 = id & 15;
        *(float4*)(Bhi + row * ROWB + c16 * 16) = sh[id];
        *(float4*)(Blo + row * ROWB + c16 * 16) = sl[id];
    }
}

__device__ __forceinline__ void clear_acc(float acc[2][8][4]) {
#pragma unroll
    for (int m = 0; m < 2; ++m)
#pragma unroll
        for (int n = 0; n < 8; ++n)
#pragma unroll
            for (int c = 0; c < 4; ++c) acc[m][n][c] = 0.f;
}

__device__ __forceinline__ void gemm_unit(float acc[2][8][4],
                                          uint32_t AHI, uint32_t ALO,
                                          uint32_t BHI, uint32_t BLO,
                                          uint32_t aoff, uint32_t boff) {
#pragma unroll
    for (int k0 = 0; k0 < 128; k0 += 16) {
        uint32_t ah[2][4], al[2][4];
        ldsm4(ah[0], AHI + aoff + k0 * 2);
        ldsm4(ah[1], AHI + aoff + 16 * ROWB + k0 * 2);
        ldsm4(al[0], ALO + aoff + k0 * 2);
        ldsm4(al[1], ALO + aoff + 16 * ROWB + k0 * 2);
#pragma unroll
        for (int g = 0; g < 4; ++g) {
            uint32_t bh[4], bl[4];
            ldsm4(bh, BHI + boff + g * 16 * ROWB + k0 * 2);
            ldsm4(bl, BLO + boff + g * 16 * ROWB + k0 * 2);
#pragma unroll
            for (int t = 0; t < 2; ++t) {
                int nt = g * 2 + t;
#pragma unroll
                for (int mt = 0; mt < 2; ++mt) {
                    mma16816(acc[mt][nt], ah[mt], bh + t * 2);
                    mma16816(acc[mt][nt], ah[mt], bl + t * 2);
                    mma16816(acc[mt][nt], al[mt], bh + t * 2);
                }
            }
        }
    }
}

__device__ __forceinline__ void epi_relu(float acc[2][8][4],
                                         const float* __restrict__ sbias,
                                         unsigned char* Ahi, unsigned char* Alo,
                                         int warp_m, int warp_n, int lane) {
    int rbase = warp_m * 32 + (lane >> 2);
    int cbase = warp_n * 64 + 2 * (lane & 3);
#pragma unroll
    for (int mt = 0; mt < 2; ++mt) {
#pragma unroll
        for (int nt = 0; nt < 8; ++nt) {
            int c = cbase + nt * 8;
            float bb0 = sbias[c], bb1 = sbias[c + 1];
            int r0 = rbase + mt * 16;
            float v0 = fmaxf(acc[mt][nt][0] + bb0, 0.f);
            float v1 = fmaxf(acc[mt][nt][1] + bb1, 0.f);
            float v2 = fmaxf(acc[mt][nt][2] + bb0, 0.f);
            float v3 = fmaxf(acc[mt][nt][3] + bb1, 0.f);
            uint32_t lo;
            uint32_t hi = pack_hilo(v0, v1, lo);
            *(uint32_t*)(Ahi + r0 * ROWB + c * 2) = hi;
            *(uint32_t*)(Alo + r0 * ROWB + c * 2) = lo;
            hi = pack_hilo(v2, v3, lo);
            *(uint32_t*)(Ahi + (r0 + 8) * ROWB + c * 2) = hi;
            *(uint32_t*)(Alo + (r0 + 8) * ROWB + c * 2) = lo;
        }
    }
}

#define SMEM_AOFF 5120
#define SMEM_TOTAL_MLP (SMEM_AOFF + 4 * TILE_BYTES_PAD)   // 144384

__global__ __launch_bounds__(256, 1)
void mlp_mma_kernel(const float* __restrict__ x,
                    const float* __restrict__ b0v,
                    const float* __restrict__ bhv,
                    const float* __restrict__ bov,
                    const float* __restrict__ gnw, const float* __restrict__ gnb,
                    float* __restrict__ out, int nNodes) {
    extern __shared__ unsigned char smem[];
    float* sb   = (float*)smem;            // [4][128] biases: b0, bh0, bh1, bo
    float* sgw  = (float*)(smem + 2048);
    float* sgb  = (float*)(smem + 2560);
    float* ps   = (float*)(smem + 3072);   // [2][128]
    float* pq   = (float*)(smem + 4096);   // [2][128]
    unsigned char* Ahi = smem + SMEM_AOFF;
    unsigned char* Alo = Ahi + TILE_BYTES_PAD;
    unsigned char* Bhi = Alo + TILE_BYTES_PAD;
    unsigned char* Blo = Bhi + TILE_BYTES_PAD;

    const uint32_t sb32 = smem_to_u32(smem);
    const uint32_t AHI = sb32 + SMEM_AOFF;
    const uint32_t ALO = AHI + TILE_BYTES_PAD;
    const uint32_t BHI = ALO + TILE_BYTES_PAD;
    const uint32_t BLO = BHI + TILE_BYTES_PAD;

    const int tid = threadIdx.x;
    const int wid = tid >> 5, lane = tid & 31;
    const int warp_m = wid & 3, warp_n = wid >> 2;
    const int m0 = blockIdx.x * 128;

    const uint32_t aoff =
        (uint32_t)(warp_m * 32 + (lane & 15)) * ROWB + (((lane >> 4) & 1) * 8) * 2;
    const uint32_t boff =
        (uint32_t)(warp_n * 64 + ((lane >> 4) & 1) * 8 + (lane & 7)) * ROWB +
        (((lane >> 3) & 1) * 8) * 2;

    if (tid < 128) {
        sb[tid]       = b0v[tid];
        sb[128 + tid] = bhv[tid];
        sb[256 + tid] = bhv[128 + tid];
        sb[384 + tid] = bov[tid];
        sgw[tid] = gnw[tid];
        sgb[tid] = gnb[tid];
    }

    float acc[2][8][4];
    clear_acc(acc);

    // ---- layer 0, part 1: A = x, B = W0[k<128] ----
    stage_A(x, m0, nNodes, Ahi, Alo, tid);
    stage_B(0, Bhi, Blo, tid);
    __syncthreads();
    gemm_unit(acc, AHI, ALO, BHI, BLO, aoff, boff);
    __syncthreads();

    // ---- layer 0, part 2: A = msg, B = W0[k>=128] (accumulate) ----
    stage_A((const float*)g_msg, m0, nNodes, Ahi, Alo, tid);
    stage_B(1, Bhi, Blo, tid);
    __syncthreads();
    gemm_unit(acc, AHI, ALO, BHI, BLO, aoff, boff);
    __syncthreads();

    // ---- hidden layers ----
#pragma unroll
    for (int l = 0; l < 2; ++l) {
        epi_relu(acc, sb + l * 128, Ahi, Alo, warp_m, warp_n, lane);
        stage_B(2 + l, Bhi, Blo, tid);
        __syncthreads();
        clear_acc(acc);
        gemm_unit(acc, AHI, ALO, BHI, BLO, aoff, boff);
        __syncthreads();
    }

    // ---- output layer ----
    epi_relu(acc, sb + 256, Ahi, Alo, warp_m, warp_n, lane);
    stage_B(4, Bhi, Blo, tid);
    __syncthreads();
    clear_acc(acc);
    gemm_unit(acc, AHI, ALO, BHI, BLO, aoff, boff);

    // ---- GroupNorm + affine + residual ----
    const int rq = lane >> 2;
    const int cbase = warp_n * 64 + 2 * (lane & 3);
#pragma unroll
    for (int mt = 0; mt < 2; ++mt)
#pragma unroll
        for (int nt = 0; nt < 8; ++nt) {
            int c = cbase + nt * 8;
            acc[mt][nt][0] += sb[384 + c];
            acc[mt][nt][1] += sb[384 + c + 1];
            acc[mt][nt][2] += sb[384 + c];
            acc[mt][nt][3] += sb[384 + c + 1];
        }
    float s[4] = {0.f, 0.f, 0.f, 0.f}, q[4] = {0.f, 0.f, 0.f, 0.f};
#pragma unroll
    for (int mt = 0; mt < 2; ++mt)
#pragma unroll
        for (int nt = 0; nt < 8; ++nt) {
            float a0 = acc[mt][nt][0], a1 = acc[mt][nt][1];
            float a2 = acc[mt][nt][2], a3 = acc[mt][nt][3];
            s[mt * 2]     += a0 + a1;
            q[mt * 2]     += a0 * a0 + a1 * a1;
            s[mt * 2 + 1] += a2 + a3;
            q[mt * 2 + 1] += a2 * a2 + a3 * a3;
        }
#pragma unroll
    for (int off = 1; off <= 2; off <<= 1) {
#pragma unroll
        for (int i = 0; i < 4; ++i) {
            s[i] += __shfl_xor_sync(0xffffffffu, s[i], off);
            q[i] += __shfl_xor_sync(0xffffffffu, q[i], off);
        }
    }
    if ((lane & 3) == 0) {
        int r0 = warp_m * 32 + rq;
        ps[warp_n * 128 + r0]      = s[0];
        ps[warp_n * 128 + r0 + 8]  = s[1];
        ps[warp_n * 128 + r0 + 16] = s[2];
        ps[warp_n * 128 + r0 + 24] = s[3];
        pq[warp_n * 128 + r0]      = q[0];
        pq[warp_n * 128 + r0 + 8]  = q[1];
        pq[warp_n * 128 + r0 + 16] = q[2];
        pq[warp_n * 128 + r0 + 24] = q[3];
    }
    __syncthreads();
#pragma unroll
    for (int mt = 0; mt < 2; ++mt) {
#pragma unroll
        for (int h = 0; h < 2; ++h) {
            int r = warp_m * 32 + mt * 16 + h * 8 + rq;
            float ts = ps[r] + ps[128 + r];
            float tq = pq[r] + pq[128 + r];
            float mean = ts * (1.f / 128.f);
            float var = tq * (1.f / 128.f) - mean * mean;
            float rstd = rsqrtf(var + 1e-5f);
            int node = m0 + r;
            if (node < nNodes) {
#pragma unroll
                for (int nt = 0; nt < 8; ++nt) {
                    int c = cbase + nt * 8;
                    float v0 = acc[mt][nt][h * 2 + 0];
                    float v1 = acc[mt][nt][h * 2 + 1];
                    float2 xv = *(const float2*)&x[(size_t)node * DIM + c];
                    float2 o;
                    o.x = (v0 - mean) * rstd * sgw[c]     + sgb[c]     + xv.x;
                    o.y = (v1 - mean) * rstd * sgw[c + 1] + sgb[c + 1] + xv.y;
                    *(float2*)&out[(size_t)node * DIM + c] = o;
                }
            }
        }
    }
}

// ---------------------------------------------------------------------------
extern "C" void kernel_launch(void* const* d_in, const int* in_sizes, int n_in,
                              void* d_out, int out_size) {
    const float* x  = (const float*)d_in[0];
    const float* e  = (const float*)d_in[1];
    const void*  ei = d_in[2];
    const float* W0 = (const float*)d_in[3];
    const float* b0 = (const float*)d_in[4];
    const float* Wh = (const float*)d_in[5];
    const float* bh = (const float*)d_in[6];
    const float* Wo = (const float*)d_in[7];
    const float* bo = (const float*)d_in[8];
    const float* gnw = (const float*)d_in[9];
    const float* gnb = (const float*)d_in[10];
    float* out = (float*)d_out;

    int nNodes = in_sizes[0] / DIM;
    int nEdges = in_sizes[1] / DIM;
    if (nNodes > MAX_NODES) nNodes = MAX_NODES;
    if (nEdges > MAX_EDGES) nEdges = MAX_EDGES;

    cudaFuncSetAttribute(mlp_mma_kernel, cudaFuncAttributeMaxDynamicSharedMemorySize,
                         SMEM_TOTAL_MLP);

    const int scanBlocks = (nNodes + 1023) / 1024;

    // 0) detect edge_index dtype
    detect_kernel<<<1, 1>>>((const unsigned int*)ei);

    // 1) weight prep (independent)
    prep_weights<<<5, 256>>>(W0, Wh, Wo);

    // 2) CSR build: zero counts -> histogram -> scan -> fill
    zero_cnt_kernel<<<(nNodes + 255) / 256, 256>>>(nNodes);
    hist_kernel<<<(nEdges + 255) / 256, 256>>>(ei, nEdges, nNodes);
    scan1_kernel<<<scanBlocks, 1024>>>(nNodes);
    scan2_kernel<<<1, 32>>>(scanBlocks);
    scan3_kernel<<<scanBlocks, 1024>>>(nNodes);
    fill_kernel<<<(nEdges + 255) / 256, 256>>>(ei, nEdges, nNodes);

    // 3) gather (no atomics on fat data; writes every g_msg row)
    long long gthreads = (long long)nNodes * 32;
    gather_kernel<<<(int)((gthreads + 255) / 256), 256>>>(e, nNodes);

    // 4) fused tensor-core MLP + GroupNorm + residual
    int mblocks = (nNodes + 127) / 128;
    mlp_mma_kernel<<<mblocks, 256, SMEM_TOTAL_MLP>>>(x, b0, bh, bo, gnw, gnb,
                                                     out, nNodes);
}